// round 14
// baseline (speedup 1.0000x reference)
#include <cuda_runtime.h>
#include <cuda_fp16.h>
#include <cstdint>

#define DI __device__ __forceinline__

static constexpr int BB   = 256;
static constexpr int HH   = 128;
static constexpr int GD   = 384;
static constexpr int NTREE= 1023;
static constexpr int KW   = 384;     // comb row: fp16
static constexpr int NCH  = 6;       // K chunks of 64 per tile
static constexpr size_t RT = (size_t)BB * NTREE;
static constexpr int NTILES = 16 * NTREE;   // 16368 tiles over all levels
static constexpr int GRID   = 456;          // 3 CTAs x 152 SMs, all co-resident

// ---------------- static device scratch ----------------
__device__ __half g_comb[RT * KW];                    // 201MB, per-level regions
__device__ __half g_Wb[640 * GD];
__device__ float g_bpk[640];
__device__ float g_cst[RT * HH];                      // 134MB, per-level regions (no reuse)
__device__ float g_root[BB * HH];
__device__ int   g_ready[2048];                       // per-rowblock completion counters
__device__ int   g_ticket;                            // dynamic tile dispenser

// ---------------- helpers ----------------
DI uint32_t smem_u32(const void* p){ uint32_t a;
  asm("{ .reg .u64 t; cvta.to.shared.u64 t, %1; cvt.u32.u64 %0, t; }":"=r"(a):"l"(p)); return a; }
DI uint32_t swz(uint32_t o){ return o ^ ((o >> 3) & 0x70); }
DI void cp16(uint32_t dst, const void* src){
  asm volatile("cp.async.cg.shared.global [%0], [%1], 16;"
               ::"r"(dst),"l"(__cvta_generic_to_global(src)):"memory"); }
DI float sigf(float v){ return 1.f/(1.f+__expf(-v)); }
DI void ldsm4(uint32_t* a, uint32_t addr){
  asm volatile("ldmatrix.sync.aligned.m8n8.x4.shared.b16 {%0,%1,%2,%3}, [%4];"
    : "=r"(a[0]),"=r"(a[1]),"=r"(a[2]),"=r"(a[3]) : "r"(addr)); }
DI void ldsm2(uint32_t* a, uint32_t addr){
  asm volatile("ldmatrix.sync.aligned.m8n8.x2.shared.b16 {%0,%1}, [%2];"
    : "=r"(a[0]),"=r"(a[1]) : "r"(addr)); }
DI void hmma(float* d, const uint32_t* a, const uint32_t* b){
  asm volatile("mma.sync.aligned.m16n8k16.row.col.f32.f16.f16.f32 "
    "{%0,%1,%2,%3}, {%4,%5,%6,%7}, {%8,%9}, {%0,%1,%2,%3};"
    : "+f"(d[0]),"+f"(d[1]),"+f"(d[2]),"+f"(d[3])
    : "r"(a[0]),"r"(a[1]),"r"(a[2]),"r"(a[3]), "r"(b[0]),"r"(b[1])); }
DI int ldcg_i(const int* p){ int v;
  asm volatile("ld.global.cg.b32 %0, [%1];" : "=r"(v)
               : "l"(__cvta_generic_to_global(p)) : "memory"); return v; }
DI int ldacq(const int* p){ int v;
  asm volatile("ld.acquire.gpu.global.b32 %0, [%1];" : "=r"(v)
               : "l"(__cvta_generic_to_global(p)) : "memory"); return v; }
DI void red_release(int* p, int v){
  asm volatile("red.release.gpu.global.add.s32 [%0], %1;"
               :: "l"(__cvta_generic_to_global(p)), "r"(v) : "memory"); }

// ---------------- reset dependency counters + ticket (each graph replay) ----------------
__global__ void reset_ready() {
    int i = blockIdx.x * blockDim.x + threadIdx.x;
    if (i < 2048) g_ready[i] = 0;
    if (i == 0) g_ticket = 0;
}

// ---------------- pack weights: packed n = (h>>3)*40 + g*8 + (h&7) ----------------
__global__ void pack_w(const float* __restrict__ Wi, const float* __restrict__ bi,
                       const float* __restrict__ Wfl,const float* __restrict__ bfl,
                       const float* __restrict__ Wfr,const float* __restrict__ bfr,
                       const float* __restrict__ Wo, const float* __restrict__ bo,
                       const float* __restrict__ Wu, const float* __restrict__ bu) {
    const float* Ws[5] = {Wi, Wfl, Wfr, Wo, Wu};
    const float* bs[5] = {bi, bfl, bfr, bo, bu};
    int idx = blockIdx.x * blockDim.x + threadIdx.x;
    if (idx < 640 * GD) {
        int nn = idx / GD, k = idx % GD;
        int hoct = nn / 40, rem = nn % 40, g = rem / 8, h3 = rem % 8;
        g_Wb[idx] = __float2half(Ws[g][(hoct * 8 + h3) * GD + k]);
    }
    if (idx < 640) {
        int hoct = idx / 40, rem = idx % 40, g = rem / 8, h3 = rem % 8;
        g_bpk[idx] = bs[g][hoct * 8 + h3];
    }
}

// ---------------- build x part of comb for ALL levels ----------------
__global__ void build_x_all(const float* __restrict__ x) {
    size_t idx = (size_t)blockIdx.x * blockDim.x + threadIdx.x;
    if (idx >= RT * 32) return;
    size_t rr = idx >> 5;
    int q = (int)(idx & 31);
    int d = 31 - __clz((int)(rr >> 8) + 1);
    int n = 1 << d;
    int r_in = (int)(rr - ((size_t)256 * (n - 1)));
    int b = r_in >> d, j = r_in & (n - 1);
    float4 v = reinterpret_cast<const float4*>(x)[((size_t)b * NTREE + (n - 1 + j)) * 32 + q];
    __half hb[4];
    hb[0] = __float2half(v.x); hb[1] = __float2half(v.y);
    hb[2] = __float2half(v.z); hb[3] = __float2half(v.w);
    __half* row = g_comb + rr * KW;
    *reinterpret_cast<uint2*>(row + q * 4) = *reinterpret_cast<uint2*>(hb);
    if (d == 9) {
        uint4 z = make_uint4(0, 0, 0, 0);
        *reinterpret_cast<uint4*>(row + 128 + q * 8) = z;
    }
}

// ---------------- fully-fused tree kernel (dynamic tickets) ----------------
// One launch for all 10 levels. Tile = 128 rows x 80 packed cols; 8 warps; 3 CTAs/SM.
// Tiles dispensed in queue order (level 9 first ... level 0 last) via atomic ticket.
// Dependencies: rowblock k of level d gates on rowblocks 2k,2k+1 of level d+1.
static constexpr uint32_t STAGE_A = 128 * 128;           // 16384
static constexpr uint32_t STAGE   = STAGE_A + 80 * 128;  // 26624
static constexpr uint32_t SMEM_BYTES = 2 * STAGE;        // 53248 (x3 = 160KB/SM)

__global__ void __launch_bounds__(256, 3) tree_fused(int ntiles)
{
    extern __shared__ char smem[];
    __shared__ int s_tile;
    const uint32_t sb = smem_u32(smem);
    const int tid = threadIdx.x, wid = tid >> 5, lane = tid & 31;
    const int warpM = wid >> 1, warpN = wid & 1;

    // ldmatrix lane addressing
    const int mat = lane >> 3;
    const int lrow = (mat & 1) * 8 + (lane & 7);
    const int lkb  = (mat >> 1) * 16;
    const int a_row0 = warpM * 32 + lrow;
    const int b_row0 = warpN * 40 + lrow;
    const int b2row  = warpN * 40 + 32 + (lane & 7);
    const int b2kb   = ((lane >> 3) & 1) * 16;

    while (true) {
        if (tid == 0) s_tile = atomicAdd(&g_ticket, 1);
        __syncthreads();
        const int t = s_tile;
        if (t >= ntiles) break;

        // ---- decode tile -> (level d, tile-in-level rem) ----
        int rem = t, d;
        for (d = 9; d > 0; d--) { int Td = 16 << d; if (rem < Td) break; rem -= Td; }
        const int n = 1 << d;
        const int bm = (rem >> 3) * 128, blkh = rem & 7;
        const size_t cur_off = (size_t)256 * ((size_t)n - 1);        // level d rows
        const size_t chd_off = (size_t)256 * ((size_t)(2 * n) - 1);  // level d+1 rows
        const int has_children = (d < 9), is_root = (d == 0);
        const __half* comb_cur = g_comb + cur_off * KW;
        const float* cprev = g_cst + chd_off * HH;   // children cells (own region)
        float* cout = g_cst + cur_off * HH;          // this level's cells (own region)

        // ---- gate: wait for both child rowblocks (8 blkh-tiles each) ----
        if (has_children) {
            const int crb = 2 * ((2 << d) - 1) + (bm >> 6);
            if (tid == 0) {
                while (ldcg_i(&g_ready[crb])     < 8) __nanosleep(64);
                while (ldcg_i(&g_ready[crb + 1]) < 8) __nanosleep(64);
                (void)ldacq(&g_ready[crb]);   // acquire once after pass
            }
            __syncthreads();
        }

        // ---- GEMM: 6 chunks, 2-stage cp.async pipeline ----
        auto load_chunk = [&](int ch) {
            const uint32_t base = sb + (uint32_t)(ch & 1) * STAGE;
            const int kk = ch * 64;
            const __half* abase = comb_cur + (size_t)bm * KW + kk;
            #pragma unroll
            for (int l = 0; l < 4; l++) {
                int tt = tid + l * 256; int row = tt >> 3, c = tt & 7;
                cp16(base + swz(row * 128 + c * 16),
                     reinterpret_cast<const char*>(abase + (size_t)row * KW) + c * 16);
            }
            const __half* bbase = g_Wb + (size_t)(blkh * 80) * GD + kk;
            #pragma unroll
            for (int l = 0; l < 3; l++) {
                int tt = tid + l * 256;
                if (tt < 640) {
                    int row = tt >> 3, c = tt & 7;
                    cp16(base + STAGE_A + swz(row * 128 + c * 16),
                         reinterpret_cast<const char*>(bbase + (size_t)row * GD) + c * 16);
                }
            }
            asm volatile("cp.async.commit_group;" ::: "memory");
        };

        float acc[2][5][4];
        #pragma unroll
        for (int a = 0; a < 2; a++)
          #pragma unroll
          for (int b = 0; b < 5; b++)
            #pragma unroll
            for (int c = 0; c < 4; c++) acc[a][b][c] = 0.f;

        load_chunk(0);
        #pragma unroll
        for (int i = 0; i < NCH; i++) {
            asm volatile("cp.async.wait_group 0;" ::: "memory");
            __syncthreads();
            if (i + 1 < NCH) load_chunk(i + 1);
            const uint32_t base = sb + (uint32_t)(i & 1) * STAGE;
            #pragma unroll
            for (int kk = 0; kk < 4; kk++) {
                uint32_t bf[5][2];
                {
                    uint32_t r[4];
                    uint32_t o = (uint32_t)(b_row0 * 128 + kk * 32 + lkb);
                    ldsm4(r, base + STAGE_A + swz(o));
                    bf[0][0] = r[0]; bf[0][1] = r[2];
                    bf[1][0] = r[1]; bf[1][1] = r[3];
                    uint32_t o1 = (uint32_t)((b_row0 + 16) * 128 + kk * 32 + lkb);
                    ldsm4(r, base + STAGE_A + swz(o1));
                    bf[2][0] = r[0]; bf[2][1] = r[2];
                    bf[3][0] = r[1]; bf[3][1] = r[3];
                    uint32_t o2 = (uint32_t)(b2row * 128 + kk * 32 + b2kb);
                    ldsm2(bf[4], base + STAGE_A + swz(o2));
                }
                #pragma unroll
                for (int mi = 0; mi < 2; mi++) {
                    uint32_t a[4];
                    uint32_t o = (uint32_t)((a_row0 + mi * 16) * 128 + kk * 32 + lkb);
                    ldsm4(a, base + swz(o));
                    #pragma unroll
                    for (int j = 0; j < 5; j++) hmma(acc[mi][j], a, bf[j]);
                }
            }
        }

        // ---- epilogue ----
        const size_t par_off = (d > 0) ? (size_t)256 * ((size_t)(n >> 1) - 1) : 0;
        const float* bp = g_bpk + blkh * 80 + warpN * 40;
        const int h0 = (blkh * 2 + warpN) * 8 + (lane & 3) * 2;
        #pragma unroll
        for (int mi = 0; mi < 2; mi++) {
            #pragma unroll
            for (int cp = 0; cp < 2; cp++) {
                int r = bm + warpM * 32 + mi * 16 + (lane >> 2) + cp * 8;
                int b_ = r >> d, j_ = r & (n - 1);
                float2 clr2 = make_float2(0.f, 0.f), crr2 = make_float2(0.f, 0.f);
                if (has_children) {
                    size_t chL = ((size_t)b_ * (2 * n) + 2 * j_) * HH;
                    clr2 = __ldcg(reinterpret_cast<const float2*>(cprev + chL + h0));
                    crr2 = __ldcg(reinterpret_cast<const float2*>(cprev + chL + HH + h0));
                }
                float ccv[2], hhv[2];
                #pragma unroll
                for (int e = 0; e < 2; e++) {
                    int c = cp * 2 + e;
                    int hs = (lane & 3) * 2 + e;
                    float vi  = sigf(acc[mi][0][c] + bp[ 0 + hs]);
                    float vfl = sigf(acc[mi][1][c] + bp[ 8 + hs]);
                    float vfr = sigf(acc[mi][2][c] + bp[16 + hs]);
                    float vo  = sigf(acc[mi][3][c] + bp[24 + hs]);
                    float vu  = tanhf(acc[mi][4][c] + bp[32 + hs]);
                    float cl = e ? clr2.y : clr2.x;
                    float cr = e ? crr2.y : crr2.x;
                    float cc = vi * vu + vfl * cl + vfr * cr;
                    ccv[e] = cc;
                    hhv[e] = vo * tanhf(cc);
                }
                *reinterpret_cast<float2*>(cout + (size_t)r * HH + h0) =
                    make_float2(ccv[0], ccv[1]);
                if (is_root) {
                    *reinterpret_cast<float2*>(g_root + (size_t)r * HH + h0) =
                        make_float2(hhv[0], hhv[1]);
                } else {
                    __half2 hp = __floats2half2_rn(hhv[0], hhv[1]);
                    __half* pc = g_comb + (par_off + (size_t)b_ * (n >> 1) + (j_ >> 1)) * KW
                                 + 128 + (j_ & 1) * 128;
                    *reinterpret_cast<__half2*>(pc + h0) = hp;
                }
            }
        }

        // ---- publish completion (release covers all CTA writes via the barrier) ----
        __syncthreads();
        if (tid == 0)
            red_release(&g_ready[2 * ((1 << d) - 1) + (bm >> 7)], 1);
    }
}

// ---------------- final classifier ----------------
__global__ void cls_kernel(const float* __restrict__ Wc, const float* __restrict__ bc,
                           float* __restrict__ out) {
    int idx = blockIdx.x * blockDim.x + threadIdx.x;
    if (idx >= BB * 5) return;
    int b = idx / 5, cc = idx % 5;
    const float* hr = g_root + (size_t)b * HH;
    float s = bc[cc];
    #pragma unroll 4
    for (int h = 0; h < HH; h++) s += hr[h] * Wc[cc * HH + h];
    out[idx] = s;
}

// ---------------- launch ----------------
extern "C" void kernel_launch(void* const* d_in, const int* in_sizes, int n_in,
                              void* d_out, int out_size) {
    (void)in_sizes; (void)n_in; (void)out_size;
    const float* x = (const float*)d_in[0];

    cudaFuncSetAttribute(tree_fused, cudaFuncAttributeMaxDynamicSharedMemorySize, SMEM_BYTES);

    reset_ready<<<8, 256>>>();

    pack_w<<<(640 * GD + 255) / 256, 256>>>(
        (const float*)d_in[1], (const float*)d_in[2],
        (const float*)d_in[3], (const float*)d_in[4],
        (const float*)d_in[5], (const float*)d_in[6],
        (const float*)d_in[7], (const float*)d_in[8],
        (const float*)d_in[9], (const float*)d_in[10]);

    build_x_all<<<(unsigned)((RT * 32 + 255) / 256), 256>>>(x);

    tree_fused<<<GRID, 256, SMEM_BYTES>>>(NTILES);

    cls_kernel<<<(BB * 5 + 127) / 128, 128>>>(
        (const float*)d_in[11], (const float*)d_in[12], (float*)d_out);
}

// round 15
// speedup vs baseline: 1.1328x; 1.1328x over previous
#include <cuda_runtime.h>
#include <cuda_fp16.h>
#include <cstdint>

#define DI __device__ __forceinline__

static constexpr int BB   = 256;
static constexpr int HH   = 128;
static constexpr int GD   = 384;
static constexpr int NTREE= 1023;
static constexpr int KW   = 384;     // comb row: fp16
static constexpr int NCH  = 6;       // K chunks of 64 per tile
static constexpr size_t RT = (size_t)BB * NTREE;
static constexpr int GRID_BIG  = 456;   // per-level kernels (3 CTAs x 152 SMs)
static constexpr int GRID_TAIL = 448;   // merged tail kernel (co-resident, margin)

// ---------------- static device scratch ----------------
__device__ __half g_comb[RT * KW];                    // 201MB, per-level regions
__device__ __half g_Wb[640 * GD];
__device__ float g_bpk[640];
__device__ float g_cst[RT * HH];                      // 134MB, per-level regions
__device__ float g_root[BB * HH];
__device__ int   g_bar;                               // grid barrier counter (tail kernel)

// ---------------- helpers ----------------
DI uint32_t smem_u32(const void* p){ uint32_t a;
  asm("{ .reg .u64 t; cvta.to.shared.u64 t, %1; cvt.u32.u64 %0, t; }":"=r"(a):"l"(p)); return a; }
DI uint32_t swz(uint32_t o){ return o ^ ((o >> 3) & 0x70); }
DI void cp16(uint32_t dst, const void* src){
  asm volatile("cp.async.cg.shared.global [%0], [%1], 16;"
               ::"r"(dst),"l"(__cvta_generic_to_global(src)):"memory"); }
DI float sigf(float v){ return 1.f/(1.f+__expf(-v)); }
DI void ldsm4(uint32_t* a, uint32_t addr){
  asm volatile("ldmatrix.sync.aligned.m8n8.x4.shared.b16 {%0,%1,%2,%3}, [%4];"
    : "=r"(a[0]),"=r"(a[1]),"=r"(a[2]),"=r"(a[3]) : "r"(addr)); }
DI void ldsm2(uint32_t* a, uint32_t addr){
  asm volatile("ldmatrix.sync.aligned.m8n8.x2.shared.b16 {%0,%1}, [%2];"
    : "=r"(a[0]),"=r"(a[1]) : "r"(addr)); }
DI void hmma(float* d, const uint32_t* a, const uint32_t* b){
  asm volatile("mma.sync.aligned.m16n8k16.row.col.f32.f16.f16.f32 "
    "{%0,%1,%2,%3}, {%4,%5,%6,%7}, {%8,%9}, {%0,%1,%2,%3};"
    : "+f"(d[0]),"+f"(d[1]),"+f"(d[2]),"+f"(d[3])
    : "r"(a[0]),"r"(a[1]),"r"(a[2]),"r"(a[3]), "r"(b[0]),"r"(b[1])); }
DI int ldcg_i(const int* p){ int v;
  asm volatile("ld.global.cg.b32 %0, [%1];" : "=r"(v)
               : "l"(__cvta_generic_to_global(p)) : "memory"); return v; }
DI int ldacq(const int* p){ int v;
  asm volatile("ld.acquire.gpu.global.b32 %0, [%1];" : "=r"(v)
               : "l"(__cvta_generic_to_global(p)) : "memory"); return v; }
DI void red_release(int* p, int v){
  asm volatile("red.release.gpu.global.add.s32 [%0], %1;"
               :: "l"(__cvta_generic_to_global(p)), "r"(v) : "memory"); }

// ---------------- reset barrier counter (each graph replay) ----------------
__global__ void reset_bar() { if (threadIdx.x == 0) g_bar = 0; }

// ---------------- pack weights: packed n = (h>>3)*40 + g*8 + (h&7) ----------------
__global__ void pack_w(const float* __restrict__ Wi, const float* __restrict__ bi,
                       const float* __restrict__ Wfl,const float* __restrict__ bfl,
                       const float* __restrict__ Wfr,const float* __restrict__ bfr,
                       const float* __restrict__ Wo, const float* __restrict__ bo,
                       const float* __restrict__ Wu, const float* __restrict__ bu) {
    const float* Ws[5] = {Wi, Wfl, Wfr, Wo, Wu};
    const float* bs[5] = {bi, bfl, bfr, bo, bu};
    int idx = blockIdx.x * blockDim.x + threadIdx.x;
    if (idx < 640 * GD) {
        int nn = idx / GD, k = idx % GD;
        int hoct = nn / 40, rem = nn % 40, g = rem / 8, h3 = rem % 8;
        g_Wb[idx] = __float2half(Ws[g][(hoct * 8 + h3) * GD + k]);
    }
    if (idx < 640) {
        int hoct = idx / 40, rem = idx % 40, g = rem / 8, h3 = rem % 8;
        g_bpk[idx] = bs[g][hoct * 8 + h3];
    }
}

// ---------------- build x part of comb for ALL levels ----------------
__global__ void build_x_all(const float* __restrict__ x) {
    size_t idx = (size_t)blockIdx.x * blockDim.x + threadIdx.x;
    if (idx >= RT * 32) return;
    size_t rr = idx >> 5;
    int q = (int)(idx & 31);
    int d = 31 - __clz((int)(rr >> 8) + 1);
    int n = 1 << d;
    int r_in = (int)(rr - ((size_t)256 * (n - 1)));
    int b = r_in >> d, j = r_in & (n - 1);
    float4 v = reinterpret_cast<const float4*>(x)[((size_t)b * NTREE + (n - 1 + j)) * 32 + q];
    __half hb[4];
    hb[0] = __float2half(v.x); hb[1] = __float2half(v.y);
    hb[2] = __float2half(v.z); hb[3] = __float2half(v.w);
    __half* row = g_comb + rr * KW;
    *reinterpret_cast<uint2*>(row + q * 4) = *reinterpret_cast<uint2*>(hb);
    if (d == 9) {
        uint4 z = make_uint4(0, 0, 0, 0);
        *reinterpret_cast<uint4*>(row + 128 + q * 8) = z;
    }
}

// ---------------- one level, R11-style persistent tiles + linearized prefetch --------
// Tile = 128 rows x 80 packed cols; 8 warps; per CTA: tiles {bid, bid+G, ...} with the
// chunk stream linearized across tiles (single pipeline prime per level per CTA).
static constexpr uint32_t STAGE_A = 128 * 128;           // 16384
static constexpr uint32_t STAGE   = STAGE_A + 80 * 128;  // 26624
static constexpr uint32_t SMEM_BYTES = 2 * STAGE;        // 53248 (x3 = 160KB/SM)

DI void run_level(uint32_t sb, int d, int gstride)
{
    const int tid = threadIdx.x, wid = tid >> 5, lane = tid & 31;
    const int warpM = wid >> 1, warpN = wid & 1;

    // ldmatrix lane addressing
    const int mat = lane >> 3;
    const int lrow = (mat & 1) * 8 + (lane & 7);
    const int lkb  = (mat >> 1) * 16;
    const int a_row0 = warpM * 32 + lrow;
    const int b_row0 = warpN * 40 + lrow;
    const int b2row  = warpN * 40 + 32 + (lane & 7);
    const int b2kb   = ((lane >> 3) & 1) * 16;

    const int n = 1 << d;
    const int ntiles = 16 << d;
    const size_t cur_off = (size_t)256 * ((size_t)n - 1);
    const size_t chd_off = (size_t)256 * ((size_t)(2 * n) - 1);
    const size_t par_off = (d > 0) ? (size_t)256 * ((size_t)(n >> 1) - 1) : 0;
    const int has_children = (d < 9), is_root = (d == 0);
    const __half* comb_cur = g_comb + cur_off * KW;
    const float* cprev = g_cst + chd_off * HH;
    float* cout = g_cst + cur_off * HH;

    const int bid = (int)blockIdx.x;
    const int my_nt = (ntiles > bid) ? (ntiles - bid + gstride - 1) / gstride : 0;
    if (my_nt == 0) return;
    const int Q = my_nt * NCH;

    int lq = 0;   // load cursor (chunk stream linear across this CTA's tiles)
    auto load_chunk = [&]() {
        if (lq >= Q) return;
        const uint32_t base = sb + (uint32_t)(lq & 1) * STAGE;
        const int lt6 = lq / NCH;
        const int lch = lq - lt6 * NCH;
        const int ltile = bid + lt6 * gstride;
        const int bm = (ltile >> 3) * 128, blkh = ltile & 7;
        const int kk = lch * 64;
        const __half* abase = comb_cur + (size_t)bm * KW + kk;
        #pragma unroll
        for (int l = 0; l < 4; l++) {
            int tt = tid + l * 256; int row = tt >> 3, c = tt & 7;
            cp16(base + swz(row * 128 + c * 16),
                 reinterpret_cast<const char*>(abase + (size_t)row * KW) + c * 16);
        }
        const __half* bbase = g_Wb + (size_t)(blkh * 80) * GD + kk;
        #pragma unroll
        for (int l = 0; l < 3; l++) {
            int tt = tid + l * 256;
            if (tt < 640) {
                int row = tt >> 3, c = tt & 7;
                cp16(base + STAGE_A + swz(row * 128 + c * 16),
                     reinterpret_cast<const char*>(bbase + (size_t)row * GD) + c * 16);
            }
        }
        asm volatile("cp.async.commit_group;" ::: "memory");
        lq++;
    };

    load_chunk();   // prime once per level

    int cq = 0;     // compute cursor
    for (int k = 0; k < my_nt; k++) {
        float acc[2][5][4];
        #pragma unroll
        for (int a = 0; a < 2; a++)
          #pragma unroll
          for (int b = 0; b < 5; b++)
            #pragma unroll
            for (int c = 0; c < 4; c++) acc[a][b][c] = 0.f;

        #pragma unroll
        for (int i = 0; i < NCH; i++) {
            asm volatile("cp.async.wait_group 0;" ::: "memory");
            __syncthreads();
            load_chunk();
            const uint32_t base = sb + (uint32_t)(cq & 1) * STAGE;
            #pragma unroll
            for (int kk = 0; kk < 4; kk++) {
                uint32_t bf[5][2];
                {
                    uint32_t r[4];
                    uint32_t o = (uint32_t)(b_row0 * 128 + kk * 32 + lkb);
                    ldsm4(r, base + STAGE_A + swz(o));
                    bf[0][0] = r[0]; bf[0][1] = r[2];
                    bf[1][0] = r[1]; bf[1][1] = r[3];
                    uint32_t o1 = (uint32_t)((b_row0 + 16) * 128 + kk * 32 + lkb);
                    ldsm4(r, base + STAGE_A + swz(o1));
                    bf[2][0] = r[0]; bf[2][1] = r[2];
                    bf[3][0] = r[1]; bf[3][1] = r[3];
                    uint32_t o2 = (uint32_t)(b2row * 128 + kk * 32 + b2kb);
                    ldsm2(bf[4], base + STAGE_A + swz(o2));
                }
                #pragma unroll
                for (int mi = 0; mi < 2; mi++) {
                    uint32_t a[4];
                    uint32_t o = (uint32_t)((a_row0 + mi * 16) * 128 + kk * 32 + lkb);
                    ldsm4(a, base + swz(o));
                    #pragma unroll
                    for (int j = 0; j < 5; j++) hmma(acc[mi][j], a, bf[j]);
                }
            }
            cq++;
        }

        // ---- epilogue for this tile (next tile's loads already in flight) ----
        const int tile = bid + k * gstride;
        const int bm = (tile >> 3) * 128, blkh = tile & 7;
        const float* bp = g_bpk + blkh * 80 + warpN * 40;
        const int h0 = (blkh * 2 + warpN) * 8 + (lane & 3) * 2;
        #pragma unroll
        for (int mi = 0; mi < 2; mi++) {
            #pragma unroll
            for (int cp = 0; cp < 2; cp++) {
                int r = bm + warpM * 32 + mi * 16 + (lane >> 2) + cp * 8;
                int b_ = r >> d, j_ = r & (n - 1);
                float2 clr2 = make_float2(0.f, 0.f), crr2 = make_float2(0.f, 0.f);
                if (has_children) {
                    size_t chL = ((size_t)b_ * (2 * n) + 2 * j_) * HH;
                    clr2 = __ldcg(reinterpret_cast<const float2*>(cprev + chL + h0));
                    crr2 = __ldcg(reinterpret_cast<const float2*>(cprev + chL + HH + h0));
                }
                float ccv[2], hhv[2];
                #pragma unroll
                for (int e = 0; e < 2; e++) {
                    int c = cp * 2 + e;
                    int hs = (lane & 3) * 2 + e;
                    float vi  = sigf(acc[mi][0][c] + bp[ 0 + hs]);
                    float vfl = sigf(acc[mi][1][c] + bp[ 8 + hs]);
                    float vfr = sigf(acc[mi][2][c] + bp[16 + hs]);
                    float vo  = sigf(acc[mi][3][c] + bp[24 + hs]);
                    float vu  = tanhf(acc[mi][4][c] + bp[32 + hs]);
                    float cl = e ? clr2.y : clr2.x;
                    float cr = e ? crr2.y : crr2.x;
                    float cc = vi * vu + vfl * cl + vfr * cr;
                    ccv[e] = cc;
                    hhv[e] = vo * tanhf(cc);
                }
                *reinterpret_cast<float2*>(cout + (size_t)r * HH + h0) =
                    make_float2(ccv[0], ccv[1]);
                if (is_root) {
                    *reinterpret_cast<float2*>(g_root + (size_t)r * HH + h0) =
                        make_float2(hhv[0], hhv[1]);
                } else {
                    __half2 hp = __floats2half2_rn(hhv[0], hhv[1]);
                    __half* pc = g_comb + (par_off + (size_t)b_ * (n >> 1) + (j_ >> 1)) * KW
                                 + 128 + (j_ & 1) * 128;
                    *reinterpret_cast<__half2*>(pc + h0) = hp;
                }
            }
        }
    }
}

// ---------------- per-level kernel (levels 9..7) ----------------
__global__ void __launch_bounds__(256, 3) gemm_level(int d, int gstride)
{
    extern __shared__ char smem[];
    run_level(smem_u32(smem), d, gstride);
}

// ---------------- merged tail kernel (levels 6..0, grid barrier between levels) ------
DI void grid_bar(int phase)
{
    __syncthreads();
    if (threadIdx.x == 0) {
        red_release(&g_bar, 1);
        const int tgt = GRID_TAIL * phase;
        while (ldcg_i(&g_bar) < tgt) __nanosleep(32);
        (void)ldacq(&g_bar);
    }
    __syncthreads();
}

__global__ void __launch_bounds__(256, 3) tail_levels()
{
    extern __shared__ char smem[];
    const uint32_t sb = smem_u32(smem);
    int phase = 0;
    for (int d = 6; d >= 0; d--) {
        run_level(sb, d, GRID_TAIL);
        if (d > 0) grid_bar(++phase);
    }
}

// ---------------- final classifier ----------------
__global__ void cls_kernel(const float* __restrict__ Wc, const float* __restrict__ bc,
                           float* __restrict__ out) {
    int idx = blockIdx.x * blockDim.x + threadIdx.x;
    if (idx >= BB * 5) return;
    int b = idx / 5, cc = idx % 5;
    const float* hr = g_root + (size_t)b * HH;
    float s = bc[cc];
    #pragma unroll 4
    for (int h = 0; h < HH; h++) s += hr[h] * Wc[cc * HH + h];
    out[idx] = s;
}

// ---------------- launch ----------------
extern "C" void kernel_launch(void* const* d_in, const int* in_sizes, int n_in,
                              void* d_out, int out_size) {
    (void)in_sizes; (void)n_in; (void)out_size;
    const float* x = (const float*)d_in[0];

    cudaFuncSetAttribute(gemm_level,  cudaFuncAttributeMaxDynamicSharedMemorySize, SMEM_BYTES);
    cudaFuncSetAttribute(tail_levels, cudaFuncAttributeMaxDynamicSharedMemorySize, SMEM_BYTES);

    reset_bar<<<1, 32>>>();

    pack_w<<<(640 * GD + 255) / 256, 256>>>(
        (const float*)d_in[1], (const float*)d_in[2],
        (const float*)d_in[3], (const float*)d_in[4],
        (const float*)d_in[5], (const float*)d_in[6],
        (const float*)d_in[7], (const float*)d_in[8],
        (const float*)d_in[9], (const float*)d_in[10]);

    build_x_all<<<(unsigned)((RT * 32 + 255) / 256), 256>>>(x);

    for (int d = 9; d >= 7; d--)
        gemm_level<<<GRID_BIG, 256, SMEM_BYTES>>>(d, GRID_BIG);

    tail_levels<<<GRID_TAIL, 256, SMEM_BYTES>>>();

    cls_kernel<<<(BB * 5 + 127) / 128, 128>>>(
        (const float*)d_in[11], (const float*)d_in[12], (float*)d_out);
}

// round 17
// speedup vs baseline: 1.1865x; 1.0473x over previous
#include <cuda_runtime.h>
#include <cuda_fp16.h>
#include <cstdint>

#define DI __device__ __forceinline__

static constexpr int BB   = 256;
static constexpr int HH   = 128;
static constexpr int GD   = 384;
static constexpr int NTREE= 1023;
static constexpr int KW   = 384;     // comb row: fp16
static constexpr int NCH  = 6;       // K chunks of 64 per tile
static constexpr size_t RT = (size_t)BB * NTREE;
static constexpr int GRID = 456;     // 3 CTAs x 152 SMs

// ---------------- static device scratch ----------------
__device__ __half g_comb[RT * KW];                    // 201MB, per-level regions
__device__ __half g_Wb[640 * GD];
__device__ float g_bpk[640];
__device__ float g_cst[RT * HH];                      // 134MB, per-level regions
__device__ float g_root[BB * HH];

// ---------------- helpers ----------------
DI uint32_t smem_u32(const void* p){ uint32_t a;
  asm("{ .reg .u64 t; cvta.to.shared.u64 t, %1; cvt.u32.u64 %0, t; }":"=r"(a):"l"(p)); return a; }
DI uint32_t swz(uint32_t o){ return o ^ ((o >> 3) & 0x70); }
DI void cp16(uint32_t dst, const void* src){
  asm volatile("cp.async.cg.shared.global [%0], [%1], 16;"
               ::"r"(dst),"l"(__cvta_generic_to_global(src)):"memory"); }
DI float sigf(float v){ return 1.f/(1.f+__expf(-v)); }
DI void ldsm4(uint32_t* a, uint32_t addr){
  asm volatile("ldmatrix.sync.aligned.m8n8.x4.shared.b16 {%0,%1,%2,%3}, [%4];"
    : "=r"(a[0]),"=r"(a[1]),"=r"(a[2]),"=r"(a[3]) : "r"(addr)); }
DI void ldsm2(uint32_t* a, uint32_t addr){
  asm volatile("ldmatrix.sync.aligned.m8n8.x2.shared.b16 {%0,%1}, [%2];"
    : "=r"(a[0]),"=r"(a[1]) : "r"(addr)); }
DI void hmma(float* d, const uint32_t* a, const uint32_t* b){
  asm volatile("mma.sync.aligned.m16n8k16.row.col.f32.f16.f16.f32 "
    "{%0,%1,%2,%3}, {%4,%5,%6,%7}, {%8,%9}, {%0,%1,%2,%3};"
    : "+f"(d[0]),"+f"(d[1]),"+f"(d[2]),"+f"(d[3])
    : "r"(a[0]),"r"(a[1]),"r"(a[2]),"r"(a[3]), "r"(b[0]),"r"(b[1])); }

// ---------------- fused prep: pack weights + build x parts of comb (one launch) -------
// pack: packed n = (h>>3)*40 + g*8 + (h&7)
// build: level d occupies comb rows [256*(2^d-1), 256*(2^(d+1)-1))
__global__ void prep_all(const float* __restrict__ x,
                         const float* __restrict__ Wi, const float* __restrict__ bi,
                         const float* __restrict__ Wfl,const float* __restrict__ bfl,
                         const float* __restrict__ Wfr,const float* __restrict__ bfr,
                         const float* __restrict__ Wo, const float* __restrict__ bo,
                         const float* __restrict__ Wu, const float* __restrict__ bu) {
    size_t idx = (size_t)blockIdx.x * blockDim.x + threadIdx.x;

    if (idx < 640 * GD) {
        const float* Ws[5] = {Wi, Wfl, Wfr, Wo, Wu};
        int nn = (int)idx / GD, k = (int)idx % GD;
        int hoct = nn / 40, rem = nn % 40, g = rem / 8, h3 = rem % 8;
        g_Wb[idx] = __float2half(Ws[g][(hoct * 8 + h3) * GD + k]);
    }
    if (idx < 640) {
        const float* bs[5] = {bi, bfl, bfr, bo, bu};
        int hoct = (int)idx / 40, rem = (int)idx % 40, g = rem / 8, h3 = rem % 8;
        g_bpk[idx] = bs[g][hoct * 8 + h3];
    }

    if (idx >= RT * 32) return;
    size_t rr = idx >> 5;
    int q = (int)(idx & 31);
    int d = 31 - __clz((int)(rr >> 8) + 1);
    int n = 1 << d;
    int r_in = (int)(rr - ((size_t)256 * (n - 1)));
    int b = r_in >> d, j = r_in & (n - 1);
    float4 v = reinterpret_cast<const float4*>(x)[((size_t)b * NTREE + (n - 1 + j)) * 32 + q];
    __half hb[4];
    hb[0] = __float2half(v.x); hb[1] = __float2half(v.y);
    hb[2] = __float2half(v.z); hb[3] = __float2half(v.w);
    __half* row = g_comb + rr * KW;
    *reinterpret_cast<uint2*>(row + q * 4) = *reinterpret_cast<uint2*>(hb);
    if (d == 9) {
        uint4 z = make_uint4(0, 0, 0, 0);
        *reinterpret_cast<uint4*>(row + 128 + q * 8) = z;
    }
}

// ---------------- persistent fused GEMM + LSTM epilogue (per level) ----------------
// Tile: 128 rows x 80 packed cols; 256 thr, 8 warps, 3 CTAs/SM.
// Chunk stream linearized across this CTA's tiles: one pipeline prime per level.
static constexpr uint32_t STAGE_A = 128 * 128;           // 16384
static constexpr uint32_t STAGE   = STAGE_A + 80 * 128;  // 26624
static constexpr uint32_t SMEM_BYTES = 2 * STAGE;        // 53248 (x3 = 160KB/SM)

__global__ void __launch_bounds__(256, 3) gemm_fused(
    int n, int log2n, int has_children, int is_root,
    size_t cur_off, size_t chd_off, size_t par_off, int ntiles, int gstride)
{
    extern __shared__ char smem[];
    const uint32_t sb = smem_u32(smem);
    const int tid = threadIdx.x, wid = tid >> 5, lane = tid & 31;
    const int warpM = wid >> 1, warpN = wid & 1;
    const int bid = (int)blockIdx.x;
    const __half* comb_cur = g_comb + cur_off * KW;
    const float* cprev = g_cst + chd_off * HH;
    float* cout = g_cst + cur_off * HH;

    const int my_nt = (ntiles > bid) ? (ntiles - bid + gstride - 1) / gstride : 0;
    if (my_nt == 0) return;
    const int Q = my_nt * NCH;

    // per-thread constant parts of the loader addressing (hoisted once)
    const int arow_ld = tid >> 3;           // A: row this thread loads (0..127)
    const int acol_ld = (tid & 7) * 16;     // byte column within 128B row
    const int brow_ld = tid >> 3;           // B rows loaded in 3 passes of 32 rows... (by +32 per l)

    // linearized chunk cursor: (lq, ltile, lch) advance incrementally, no division
    int lq = 0, ltile = bid, lch = 0;
    auto load_chunk = [&]() {
        if (lq >= Q) return;
        const uint32_t base = sb + (uint32_t)(lq & 1) * STAGE;
        const int bm = (ltile >> 3) * 128, blkh = ltile & 7;
        const int kk = lch * 64;
        const __half* abase = comb_cur + (size_t)bm * KW + kk;
        #pragma unroll
        for (int l = 0; l < 4; l++) {                  // A: 128 rows x 8 x 16B
            int row = arow_ld + l * 32;
            cp16(base + swz(row * 128 + acol_ld),
                 reinterpret_cast<const char*>(abase + (size_t)row * KW) + acol_ld);
        }
        const __half* bbase = g_Wb + (size_t)(blkh * 80) * GD + kk;
        #pragma unroll
        for (int l = 0; l < 3; l++) {                  // B: 80 rows x 8 x 16B
            int row = brow_ld + l * 32;
            if (row < 80)
                cp16(base + STAGE_A + swz(row * 128 + acol_ld),
                     reinterpret_cast<const char*>(bbase + (size_t)row * GD) + acol_ld);
        }
        asm volatile("cp.async.commit_group;" ::: "memory");
        lq++;
        if (++lch == NCH) { lch = 0; ltile += gstride; }
    };

    load_chunk();   // prime once per level

    // ldmatrix lane addressing
    const int mat = lane >> 3;
    const int lrow = (mat & 1) * 8 + (lane & 7);
    const int lkb  = (mat >> 1) * 16;
    const int a_row0 = warpM * 32 + lrow;
    const int b_row0 = warpN * 40 + lrow;
    const int b2row  = warpN * 40 + 32 + (lane & 7);
    const int b2kb   = ((lane >> 3) & 1) * 16;

    int cq = 0;     // compute cursor
    for (int k = 0; k < my_nt; k++) {
        float acc[2][5][4];
        #pragma unroll
        for (int a = 0; a < 2; a++)
          #pragma unroll
          for (int b = 0; b < 5; b++)
            #pragma unroll
            for (int c = 0; c < 4; c++) acc[a][b][c] = 0.f;

        #pragma unroll
        for (int i = 0; i < NCH; i++) {
            asm volatile("cp.async.wait_group 0;" ::: "memory");
            __syncthreads();
            load_chunk();
            const uint32_t base = sb + (uint32_t)(cq & 1) * STAGE;
            #pragma unroll
            for (int kk = 0; kk < 4; kk++) {
                uint32_t bf[5][2];
                {
                    uint32_t r[4];
                    uint32_t o = (uint32_t)(b_row0 * 128 + kk * 32 + lkb);
                    ldsm4(r, base + STAGE_A + swz(o));
                    bf[0][0] = r[0]; bf[0][1] = r[2];
                    bf[1][0] = r[1]; bf[1][1] = r[3];
                    uint32_t o1 = (uint32_t)((b_row0 + 16) * 128 + kk * 32 + lkb);
                    ldsm4(r, base + STAGE_A + swz(o1));
                    bf[2][0] = r[0]; bf[2][1] = r[2];
                    bf[3][0] = r[1]; bf[3][1] = r[3];
                    uint32_t o2 = (uint32_t)(b2row * 128 + kk * 32 + b2kb);
                    ldsm2(bf[4], base + STAGE_A + swz(o2));
                }
                #pragma unroll
                for (int mi = 0; mi < 2; mi++) {
                    uint32_t a[4];
                    uint32_t o = (uint32_t)((a_row0 + mi * 16) * 128 + kk * 32 + lkb);
                    ldsm4(a, base + swz(o));
                    #pragma unroll
                    for (int j = 0; j < 5; j++) hmma(acc[mi][j], a, bf[j]);
                }
            }
            cq++;
        }

        // ---- epilogue for this tile (next tile's loads already in flight) ----
        const int tile = bid + k * gstride;
        const int bm = (tile >> 3) * 128, blkh = tile & 7;
        const float* bp = g_bpk + blkh * 80 + warpN * 40;
        const int h0 = (blkh * 2 + warpN) * 8 + (lane & 3) * 2;
        #pragma unroll
        for (int mi = 0; mi < 2; mi++) {
            #pragma unroll
            for (int cp = 0; cp < 2; cp++) {
                int r = bm + warpM * 32 + mi * 16 + (lane >> 2) + cp * 8;
                int b_ = r >> log2n, j_ = r & (n - 1);
                float2 clr2 = make_float2(0.f, 0.f), crr2 = make_float2(0.f, 0.f);
                if (has_children) {
                    size_t chL = ((size_t)b_ * (2 * n) + 2 * j_) * HH;
                    clr2 = __ldcg(reinterpret_cast<const float2*>(cprev + chL + h0));
                    crr2 = __ldcg(reinterpret_cast<const float2*>(cprev + chL + HH + h0));
                }
                float ccv[2], hhv[2];
                #pragma unroll
                for (int e = 0; e < 2; e++) {
                    int c = cp * 2 + e;
                    int hs = (lane & 3) * 2 + e;
                    float vi  = sigf(acc[mi][0][c] + bp[ 0 + hs]);
                    float vfl = sigf(acc[mi][1][c] + bp[ 8 + hs]);
                    float vfr = sigf(acc[mi][2][c] + bp[16 + hs]);
                    float vo  = sigf(acc[mi][3][c] + bp[24 + hs]);
                    float vu  = tanhf(acc[mi][4][c] + bp[32 + hs]);
                    float cl = e ? clr2.y : clr2.x;
                    float cr = e ? crr2.y : crr2.x;
                    float cc = vi * vu + vfl * cl + vfr * cr;
                    ccv[e] = cc;
                    hhv[e] = vo * tanhf(cc);
                }
                __stcg(reinterpret_cast<float2*>(cout + (size_t)r * HH + h0),
                       make_float2(ccv[0], ccv[1]));
                if (is_root) {
                    __stcg(reinterpret_cast<float2*>(g_root + (size_t)r * HH + h0),
                           make_float2(hhv[0], hhv[1]));
                } else {
                    __half2 hp = __floats2half2_rn(hhv[0], hhv[1]);
                    __half* pc = g_comb + (par_off + (size_t)b_ * (n >> 1) + (j_ >> 1)) * KW
                                 + 128 + (j_ & 1) * 128;
                    __stcg(reinterpret_cast<__half2*>(pc + h0), hp);
                }
            }
        }
    }
}

// ---------------- final classifier ----------------
__global__ void cls_kernel(const float* __restrict__ Wc, const float* __restrict__ bc,
                           float* __restrict__ out) {
    int idx = blockIdx.x * blockDim.x + threadIdx.x;
    if (idx >= BB * 5) return;
    int b = idx / 5, cc = idx % 5;
    const float* hr = g_root + (size_t)b * HH;
    float s = bc[cc];
    #pragma unroll 4
    for (int h = 0; h < HH; h++) s += hr[h] * Wc[cc * HH + h];
    out[idx] = s;
}

// ---------------- launch ----------------
extern "C" void kernel_launch(void* const* d_in, const int* in_sizes, int n_in,
                              void* d_out, int out_size) {
    (void)in_sizes; (void)n_in; (void)out_size;
    const float* x = (const float*)d_in[0];

    cudaFuncSetAttribute(gemm_fused, cudaFuncAttributeMaxDynamicSharedMemorySize, SMEM_BYTES);

    prep_all<<<(unsigned)((RT * 32 + 255) / 256), 256>>>(
        x,
        (const float*)d_in[1], (const float*)d_in[2],
        (const float*)d_in[3], (const float*)d_in[4],
        (const float*)d_in[5], (const float*)d_in[6],
        (const float*)d_in[7], (const float*)d_in[8],
        (const float*)d_in[9], (const float*)d_in[10]);

    for (int d = 9; d >= 0; d--) {
        int n = 1 << d;
        size_t cur_off = (size_t)256 * ((size_t)n - 1);
        size_t chd_off = (size_t)256 * ((size_t)(2 * n) - 1);
        size_t par_off = (d > 0) ? (size_t)256 * ((size_t)(n >> 1) - 1) : 0;
        int tiles = 16 * n;
        int grid = tiles < GRID ? tiles : GRID;
        gemm_fused<<<grid, 256, SMEM_BYTES>>>(n, d, d < 9, d == 0,
                                              cur_off, chd_off, par_off, tiles, grid);
    }

    cls_kernel<<<(BB * 5 + 127) / 128, 128>>>(
        (const float*)d_in[11], (const float*)d_in[12], (float*)d_out);
}